// round 15
// baseline (speedup 1.0000x reference)
#include <cuda_runtime.h>
#include <math.h>

// Shapes fixed by the problem: B=4, C=256, H=W=64, N=4096, Ci=128
#define B_  4
#define C_  256
#define N_  4096
#define CI_ 128

// Scratch (allocation-free rule: __device__ globals)
__device__ float g_xbar[B_ * C_];   // per-(b,c) spatial mean of x
__device__ float g_w[B_ * C_];      // w[b,c] = sum_k tbar[b,k] * phi_w[k,c]
__device__ float g_s[B_];           // s[b]  = sum_k tbar[b,k] * phi_b[k]
__device__ unsigned g_flag;         // 0 after kernel1; ==4 when all w ready

// ---------------------------------------------------------------------------
// Kernel 1: xbar. 1024 blocks x 128 thr; one row per block, 8 float4 loads.
// Block 0 also resets the handshake flag for kernel 2 (stream-ordered).
// ---------------------------------------------------------------------------
__global__ __launch_bounds__(128, 10) void k_rowmean(const float* __restrict__ x) {
    if (blockIdx.x == 0 && threadIdx.x == 0) g_flag = 0u;

    const int tid  = threadIdx.x;
    const int lane = tid & 31, warp = tid >> 5;
    const int row  = blockIdx.x;

    const float4* xr = (const float4*)(x + (size_t)row * N_);

    float4 v0 = xr[tid];
    float4 v1 = xr[tid + 128];
    float4 v2 = xr[tid + 256];
    float4 v3 = xr[tid + 384];
    float4 v4 = xr[tid + 512];
    float4 v5 = xr[tid + 640];
    float4 v6 = xr[tid + 768];
    float4 v7 = xr[tid + 896];

    float a = ((v0.x + v0.y) + (v0.z + v0.w))
            + ((v1.x + v1.y) + (v1.z + v1.w))
            + ((v2.x + v2.y) + (v2.z + v2.w))
            + ((v3.x + v3.y) + (v3.z + v3.w))
            + ((v4.x + v4.y) + (v4.z + v4.w))
            + ((v5.x + v5.y) + (v5.z + v5.w))
            + ((v6.x + v6.y) + (v6.z + v6.w))
            + ((v7.x + v7.y) + (v7.z + v7.w));

    #pragma unroll
    for (int o = 16; o; o >>= 1) a += __shfl_xor_sync(0xffffffffu, a, o);
    __shared__ float ws_[4];
    if (lane == 0) ws_[warp] = a;
    __syncthreads();
    if (tid == 0)
        g_xbar[row] = (ws_[0] + ws_[1] + ws_[2] + ws_[3]) * (1.0f / N_);
}

// ---------------------------------------------------------------------------
// Kernel 2: fused (matvec-in-kernel) + dot + sigmoid + scale.
// 1024 blocks x 256 threads = (16 pixels) x (16 splits of 16 channels).
//
// Blocks 0..3 are PRODUCERS: block p computes w[p,:], s[p] from g_xbar and
// the theta/phi weights, then threadfence + atomicAdd(g_flag). Blocks 0..3
// are dispatched first, so any spinning waiter implies producers are already
// resident -> no deadlock even though grid > resident slots.
// All blocks issue their 16 independent x-loads BEFORE the spin, so DRAM
// stays busy while the 4 producer blocks run their ~1us matvec.
// ---------------------------------------------------------------------------
#define TJ_   16
#define CSPL_ 16
#define CPT_  16

__global__ __launch_bounds__(256, 4) void k_fused(
    const float* __restrict__ x,
    const float* __restrict__ theta_w, const float* __restrict__ theta_b,
    const float* __restrict__ phi_w,  const float* __restrict__ phi_b,
    float* __restrict__ out)
{
    const int tid  = threadIdx.x;
    const int lane = tid & 31, warp = tid >> 5;
    const int jloc = tid & (TJ_ - 1);
    const int csub = tid >> 4;                  // 0..15
    const int tile = blockIdx.x;                // 0..1023
    const int b    = tile >> 8;
    const int j    = (tile & 255) * TJ_ + jloc;

    __shared__ float ws[C_];
    __shared__ float part[CSPL_ * TJ_];
    __shared__ float conf_s[TJ_];
    __shared__ float sb_s;
    __shared__ float xb_s[C_];
    __shared__ float tb_s[CI_];

    // ---- Prologue: 16 independent x loads per thread (before any wait) ----
    const float* xb = x + (size_t)(b * C_) * N_ + j + (size_t)(csub * CPT_) * N_;
    float xv[CPT_];
    #pragma unroll
    for (int i = 0; i < CPT_; ++i)
        xv[i] = __ldg(xb + (size_t)i * N_);

    // ---- Producers: blocks 0..3 compute w[bp,:], s[bp] ----
    if (tile < B_) {
        const int bp = tile;
        xb_s[tid] = __ldcg(&g_xbar[bp * C_ + tid]);
        __syncthreads();
        for (int i = 0; i < CI_ / 8; ++i) {
            const int k = warp * (CI_ / 8) + i;
            const float* tw = theta_w + (size_t)k * C_;
            float a = 0.f;
            #pragma unroll
            for (int c = lane; c < C_; c += 32) a += __ldg(tw + c) * xb_s[c];
            #pragma unroll
            for (int o = 16; o; o >>= 1) a += __shfl_xor_sync(0xffffffffu, a, o);
            if (lane == 0) tb_s[k] = a + __ldg(theta_b + k);
        }
        __syncthreads();
        float wacc = 0.f;
        #pragma unroll 8
        for (int k = 0; k < CI_; ++k)
            wacc += tb_s[k] * __ldg(phi_w + (size_t)k * C_ + tid);
        g_w[bp * C_ + tid] = wacc;
        if (warp == 0) {
            float a = 0.f;
            #pragma unroll
            for (int k = lane; k < CI_; k += 32) a += tb_s[k] * __ldg(phi_b + k);
            #pragma unroll
            for (int o = 16; o; o >>= 1) a += __shfl_xor_sync(0xffffffffu, a, o);
            if (lane == 0) g_s[bp] = a;
        }
        __threadfence();                         // publish g_w/g_s
        __syncthreads();
        if (tid == 0) atomicAdd(&g_flag, 1u);
    }

    // ---- All blocks: wait for all 4 producers ----
    if (tid == 0) {
        volatile unsigned* fp = &g_flag;
        while (*fp < (unsigned)B_) __nanosleep(64);
    }
    __syncthreads();

    // ---- Dot / sigmoid / scale from register-cached x ----
    ws[tid] = __ldcg(&g_w[b * C_ + tid]);
    if (tid == 0) sb_s = __ldcg(&g_s[b]);
    __syncthreads();

    float acc = 0.f;
    #pragma unroll
    for (int i = 0; i < CPT_; ++i) acc += ws[csub * CPT_ + i] * xv[i];
    part[csub * TJ_ + jloc] = acc;
    __syncthreads();

    if (tid < TJ_) {
        float m = 0.f;
        #pragma unroll
        for (int k = 0; k < CSPL_; ++k) m += part[k * TJ_ + tid];
        m = (m + sb_s) * (1.0f / N_);
        conf_s[tid] = 1.0f / (1.0f + expf(-m));
    }
    __syncthreads();

    const float cf = conf_s[jloc];
    float* ob = out + (size_t)(b * C_) * N_ + j + (size_t)(csub * CPT_) * N_;
    #pragma unroll
    for (int i = 0; i < CPT_; ++i)
        ob[(size_t)i * N_] = cf * xv[i];
}

// ---------------------------------------------------------------------------
extern "C" void kernel_launch(void* const* d_in, const int* in_sizes, int n_in,
                              void* d_out, int out_size) {
    const float* x       = (const float*)d_in[0];
    const float* theta_w = (const float*)d_in[1];
    const float* theta_b = (const float*)d_in[2];
    const float* phi_w   = (const float*)d_in[3];
    const float* phi_b   = (const float*)d_in[4];
    float* out = (float*)d_out;

    k_rowmean<<<B_ * C_, 128>>>(x);
    k_fused<<<1024, 256>>>(x, theta_w, theta_b, phi_w, phi_b, out);
}